// round 7
// baseline (speedup 1.0000x reference)
#include <cuda_runtime.h>
#include <math_constants.h>

// Problem constants
#define NUM_VARS 64
#define KK       32
#define NUM_CATS 256
#define NUM_INPUT (NUM_VARS * KK)   // 2048
#define LL       4
#define EE       16384
#define NN       8192
#define CC       4
#define BB       1024
#define Q4       (BB / 4)           // 256 ushort4-groups per row
#define TOTAL_NODES (NUM_INPUT + LL * NN)  // 34816
#define NCHUNK   64

#define GRID_BLOCKS 888             // 6 blocks/SM on 148 SMs — co-resident
#define THREADS     256
#define NTHREADS    (GRID_BLOCKS * THREADS)

#define LOG2E 1.4426950408889634f
#define LN2   0.6931471805599453f
#define QSCALE   128.0f             // u16 = -v_log2 * 128, clamp 32767
#define INVQ     (1.0f / 128.0f)
#define MAGIC    8388608.0f         // 2^23
#define MAGIC_HI 0x4B000000u

// Node pool quantized to u16 (71.3 MB — fully L2-resident)
__device__ unsigned short g_node_q[(size_t)TOTAL_NODES * BB];
__device__ float g_partial[NCHUNK * BB];
__device__ uint2 g_pairs[LL * NN * CC];   // pre-scaled row offsets (row * Q4)

// Grid barrier
__device__ unsigned g_bar_count;
__device__ volatile unsigned g_bar_gen;

__device__ __forceinline__ void grid_sync() {
    __syncthreads();
    if (threadIdx.x == 0) {
        __threadfence();
        unsigned gen = g_bar_gen;
        if (atomicAdd(&g_bar_count, 1u) == GRID_BLOCKS - 1u) {
            g_bar_count = 0;
            __threadfence();
            g_bar_gen = gen + 1u;
        } else {
            while (g_bar_gen == gen) { }
        }
    }
    __syncthreads();
    __threadfence();
}

__device__ __forceinline__ float ex2(float x) {
    float r; asm("ex2.approx.ftz.f32 %0, %1;" : "=f"(r) : "f"(x)); return r;
}
__device__ __forceinline__ float lg2(float x) {
    float r; asm("lg2.approx.ftz.f32 %0, %1;" : "=f"(r) : "f"(x)); return r;
}

__device__ __forceinline__ float lse4_2(float a, float b, float c, float d) {
    float m = fmaxf(fmaxf(a, b), fmaxf(c, d));
    float s = ex2(a - m) + ex2(b - m) + ex2(c - m) + ex2(d - m);
    return m + lg2(s);
}

// PRMT-based decode: one byte_perm + one FMA per value.
// lo: float bits = 0x4B00_(s.lo16); hi: 0x4B00_(s.hi16)
__device__ __forceinline__ float dec_lo(unsigned s, float wq) {
    const float f = __uint_as_float(__byte_perm(s, MAGIC_HI, 0x7610));
    return fmaf(f, -INVQ, wq);
}
__device__ __forceinline__ float dec_hi(unsigned s, float wq) {
    const float f = __uint_as_float(__byte_perm(s, MAGIC_HI, 0x7632));
    return fmaf(f, -INVQ, wq);
}

__device__ __forceinline__ unsigned enc1(float v_log2) {
    unsigned q = __float2uint_rn(-v_log2 * QSCALE);   // saturates at 0
    return umin(q, 32767u);
}

__global__ void __launch_bounds__(THREADS, 6)
circuit_kernel(const int* __restrict__ inputs,
               const float* __restrict__ input_logp,
               const int2* __restrict__ prod_ids,     // (L, E)
               const int* __restrict__ sum_ch_ids,    // (L, N, C)
               const float4* __restrict__ sum_logw,   // (L, N) as float4
               const float* __restrict__ root_logw,   // (N,)
               float* __restrict__ out) {
    const int gtid = blockIdx.x * THREADS + threadIdx.x;

    // ---------- Phase 0: input layer (quantize) + resolve (pre-scaled) --------
    for (int idx = gtid; idx < NUM_INPUT * BB; idx += NTHREADS) {
        const int v = idx >> 15;
        const int k = (idx >> 10) & (KK - 1);
        const int b = idx & (BB - 1);
        const int cat = __ldg(inputs + b * NUM_VARS + v);
        const float lp2 = __ldg(input_logp + ((v * KK + k) << 8) + cat) * LOG2E;
        g_node_q[idx] = (unsigned short)enc1(lp2);
    }
    for (int idx = gtid; idx < LL * NN * CC; idx += NTHREADS) {
        const int l = idx / (NN * CC);
        const int e = __ldg(sum_ch_ids + idx);
        const int2 p = __ldg(prod_ids + (size_t)l * EE + e);
        g_pairs[idx] = make_uint2((unsigned)p.x * Q4, (unsigned)p.y * Q4);
    }
    grid_sync();

    // ---------- Phases 1..4: sum layers (quantized gathers) -------------------
    const uint2* nq = reinterpret_cast<const uint2*>(g_node_q);
    uint2* nqo = reinterpret_cast<uint2*>(g_node_q);
    const unsigned c4 = threadIdx.x;   // ushort4-column 0..255

    for (int l = 0; l < LL; l++) {
        const int out_base = NUM_INPUT + l * NN;
        const uint4* prbase = reinterpret_cast<const uint4*>(g_pairs) + (size_t)l * NN * 2;
        const float4* lw = sum_logw + (size_t)l * NN;

        for (int n = blockIdx.x; n < NN; n += GRID_BLOCKS) {
            const uint4 pa = __ldg(prbase + n * 2);
            const uint4 pb = __ldg(prbase + n * 2 + 1);
            const float4 w = __ldg(lw + n);
            const float wq0 = fmaf(w.x, LOG2E, MAGIC * INVQ);
            const float wq1 = fmaf(w.y, LOG2E, MAGIC * INVQ);
            const float wq2 = fmaf(w.z, LOG2E, MAGIC * INVQ);
            const float wq3 = fmaf(w.w, LOG2E, MAGIC * INVQ);

            const uint2 a0 = __ldg(nq + pa.x + c4);
            const uint2 q0 = __ldg(nq + pa.y + c4);
            const uint2 a1 = __ldg(nq + pa.z + c4);
            const uint2 q1 = __ldg(nq + pa.w + c4);
            const uint2 a2 = __ldg(nq + pb.x + c4);
            const uint2 q2 = __ldg(nq + pb.y + c4);
            const uint2 a3 = __ldg(nq + pb.z + c4);
            const uint2 q3 = __ldg(nq + pb.w + c4);

            const unsigned s0x = __vadd2(a0.x, q0.x), s0y = __vadd2(a0.y, q0.y);
            const unsigned s1x = __vadd2(a1.x, q1.x), s1y = __vadd2(a1.y, q1.y);
            const unsigned s2x = __vadd2(a2.x, q2.x), s2y = __vadd2(a2.y, q2.y);
            const unsigned s3x = __vadd2(a3.x, q3.x), s3y = __vadd2(a3.y, q3.y);

            const float o0 = lse4_2(dec_lo(s0x, wq0), dec_lo(s1x, wq1),
                                    dec_lo(s2x, wq2), dec_lo(s3x, wq3));
            const float o1 = lse4_2(dec_hi(s0x, wq0), dec_hi(s1x, wq1),
                                    dec_hi(s2x, wq2), dec_hi(s3x, wq3));
            const float o2 = lse4_2(dec_lo(s0y, wq0), dec_lo(s1y, wq1),
                                    dec_lo(s2y, wq2), dec_lo(s3y, wq3));
            const float o3 = lse4_2(dec_hi(s0y, wq0), dec_hi(s1y, wq1),
                                    dec_hi(s2y, wq2), dec_hi(s3y, wq3));

            uint2 qo;
            qo.x = __byte_perm(enc1(o0), enc1(o1), 0x5410);
            qo.y = __byte_perm(enc1(o2), enc1(o3), 0x5410);
            nqo[(unsigned)(out_base + n) * Q4 + c4] = qo;
        }
        grid_sync();
    }

    // ---------- Phase 5: root partial logsumexp (decode u16) ------------------
    {
        const unsigned short* last = g_node_q + (size_t)(NUM_INPUT + (LL - 1) * NN) * BB;
        const int idx = gtid;
        if (idx < NCHUNK * BB) {
            const int chunk = idx >> 10;
            const int b = idx & (BB - 1);
            const int n0 = chunk * (NN / NCHUNK);
            float m = -CUDART_INF_F, s = 0.f;
#pragma unroll 4
            for (int i = 0; i < NN / NCHUNK; i++) {
                const int n = n0 + i;
                const float nv = -(float)last[(unsigned)n * BB + b] * INVQ;
                const float x = fmaf(__ldg(root_logw + n), LOG2E, nv);
                const float mn = fmaxf(m, x);
                s = s * ex2(m - mn) + ex2(x - mn);
                m = mn;
            }
            g_partial[chunk * BB + b] = m + lg2(s);
        }
    }
    grid_sync();

    // ---------- Phase 6: final combine (-> natural log) -----------------------
    {
        const int wgid = gtid >> 5;
        const int lane = gtid & 31;
        if (wgid < BB) {
            const int b = wgid;
            const float x0 = g_partial[lane * BB + b];
            const float x1 = g_partial[(lane + 32) * BB + b];
            float m = fmaxf(x0, x1);
#pragma unroll
            for (int o = 16; o > 0; o >>= 1)
                m = fmaxf(m, __shfl_xor_sync(0xFFFFFFFF, m, o));
            float s = ex2(x0 - m) + ex2(x1 - m);
#pragma unroll
            for (int o = 16; o > 0; o >>= 1)
                s += __shfl_xor_sync(0xFFFFFFFF, s, o);
            if (lane == 0) out[b] = (m + lg2(s)) * LN2;
        }
    }
}

// ---------------------------------------------------------------------------
extern "C" void kernel_launch(void* const* d_in, const int* in_sizes, int n_in,
                              void* d_out, int out_size) {
    const int*   inputs     = (const int*)  d_in[0];
    const float* input_logp = (const float*)d_in[1];
    const int*   prod_ids   = (const int*)  d_in[2];  // (L, E, 2)
    const int*   sum_ch_ids = (const int*)  d_in[3];  // (L, N, C)
    const float* sum_logw   = (const float*)d_in[4];  // (L, N, C)
    const float* root_logw  = (const float*)d_in[5];  // (N,)
    float* out = (float*)d_out;

    circuit_kernel<<<GRID_BLOCKS, THREADS>>>(
        inputs, input_logp,
        reinterpret_cast<const int2*>(prod_ids),
        sum_ch_ids,
        reinterpret_cast<const float4*>(sum_logw),
        root_logw, out);
}